// round 3
// baseline (speedup 1.0000x reference)
#include <cuda_runtime.h>

// CapsuleBlock: B=64, N=2048, D_in=8, K(N_out)=16, O(D_out)=16, 3 routing iters.
// R3: hats computed once (fp32 FFMA2), stored fp16 (67MB). Streaming routing
// passes. NBLK=148 (exactly one wave @ 1 block/SM). 6 graph nodes total.

#define NBLK   148
#define CHUNK  14          // 148*14 = 2072 >= 2048
#define THREADS 512        // pass1: thread = (b, kp): b=tid>>3 (64), kp=tid&7

__device__ float g_part [(size_t)NBLK * 16384];          // pass1 partials [blk][b][256]
__device__ float g_part2[(size_t)16 * 16384];            // route partials [g][b][256]
__device__ float g_route[16384];                         // routing vector [b][k][o]
__device__ __align__(16) unsigned short g_hats[(size_t)64 * 2048 * 256]; // fp16 hats

typedef unsigned long long ull;

__device__ __forceinline__ ull pack2(float v) {
    ull r; asm("mov.b64 %0, {%1, %1};" : "=l"(r) : "f"(v)); return r;
}
__device__ __forceinline__ ull fma2(ull a, ull b, ull c) {
    ull d; asm("fma.rn.f32x2 %0, %1, %2, %3;" : "=l"(d) : "l"(a), "l"(b), "l"(c)); return d;
}
__device__ __forceinline__ ull mul2(ull a, ull b) {
    ull d; asm("mul.rn.f32x2 %0, %1, %2;" : "=l"(d) : "l"(a), "l"(b)); return d;
}
__device__ __forceinline__ ull add2(ull a, ull b) {
    ull d; asm("add.rn.f32x2 %0, %1, %2;" : "=l"(d) : "l"(a), "l"(b)); return d;
}
__device__ __forceinline__ float2 unpack2(ull v) {
    float2 r; asm("mov.b64 {%0, %1}, %2;" : "=f"(r.x), "=f"(r.y) : "l"(v)); return r;
}
// pack (lo, hi) floats into f16x2 word (lo -> low half)
__device__ __forceinline__ unsigned cvtf16x2(float lo, float hi) {
    unsigned r; asm("cvt.rn.f16x2.f32 %0, %1, %2;" : "=r"(r) : "f"(hi), "f"(lo)); return r;
}
// f16x2 word -> f32x2 (low half -> low f32)
__device__ __forceinline__ ull h2f2(unsigned w) {
    ull d;
    asm("{ .reg .b16 l, h; .reg .f32 fl, fh;\n\t"
        "mov.b32 {l, h}, %1;\n\t"
        "cvt.f32.f16 fl, l;\n\t"
        "cvt.f32.f16 fh, h;\n\t"
        "mov.b64 %0, {fl, fh}; }"
        : "=l"(d) : "r"(w));
    return d;
}

// K1: hats = einsum('bd,kdo->bko') per n; acc s0 = sum_n hats; store hats fp16.
__global__ void __launch_bounds__(THREADS, 1)
pass1_kernel(const float* __restrict__ x, const float* __restrict__ W) {
    __shared__ __align__(16) float2 Ws[8][8][16];        // [d][opair][k], 8 KB
    __shared__ float xs[CHUNK][64][8];                   // 28 KB

    const int tid = threadIdx.x;
    const int b  = tid >> 3;
    const int kp = tid & 7;
    const int n0 = blockIdx.x * CHUNK;
    int nmax = 2048 - n0; if (nmax > CHUNK) nmax = CHUNK;   // may be <= 0

    for (int i = tid; i < nmax * 128; i += THREADS) {
        int ln = i >> 7, r = i & 127, bb = r >> 1, dq = r & 1;
        float4 v = *(const float4*)(x + ((size_t)bb * 2048 + (size_t)(n0 + ln)) * 8 + dq * 4);
        *(float4*)(&xs[ln][bb][dq * 4]) = v;
    }

    const int wk = tid & 15, wt = tid >> 4, wd = wt >> 2, woq = wt & 3;
    const size_t woff = (size_t)wk * 128 + (size_t)wd * 16 + (size_t)woq * 4;
    float4 wreg = make_float4(0.f, 0.f, 0.f, 0.f);
    if (nmax > 0) wreg = *(const float4*)(W + (size_t)n0 * 2048 + woff);

    ull acc0[8], acc1[8];
#pragma unroll
    for (int op = 0; op < 8; op++) { acc0[op] = 0ull; acc1[op] = 0ull; }

    for (int ln = 0; ln < nmax; ln++) {
        Ws[wd][2 * woq    ][wk] = make_float2(wreg.x, wreg.y);
        Ws[wd][2 * woq + 1][wk] = make_float2(wreg.z, wreg.w);
        __syncthreads();
        if (ln + 1 < nmax)
            wreg = *(const float4*)(W + (size_t)(n0 + ln + 1) * 2048 + woff);

        ull h0[8], h1[8];
#pragma unroll
        for (int d = 0; d < 8; d++) {
            ull xd = pack2(xs[ln][b][d]);
#pragma unroll
            for (int op = 0; op < 8; op++) {
                ulonglong2 w = *(const ulonglong2*)&Ws[d][op][2 * kp];
                if (d == 0) { h0[op] = mul2(xd, w.x); h1[op] = mul2(xd, w.y); }
                else        { h0[op] = fma2(xd, w.x, h0[op]); h1[op] = fma2(xd, w.y, h1[op]); }
            }
        }
#pragma unroll
        for (int op = 0; op < 8; op++) {
            acc0[op] = add2(acc0[op], h0[op]);
            acc1[op] = add2(acc1[op], h1[op]);
        }
        unsigned s0[8], s1[8];
#pragma unroll
        for (int op = 0; op < 8; op++) {
            float2 a = unpack2(h0[op]); s0[op] = cvtf16x2(a.x, a.y);
            float2 c = unpack2(h1[op]); s1[op] = cvtf16x2(c.x, c.y);
        }
        unsigned short* hp = g_hats + ((size_t)b * 2048 + (size_t)(n0 + ln)) * 256 + (size_t)(2 * kp) * 16;
        *(uint4*)(hp +  0) = make_uint4(s0[0], s0[1], s0[2], s0[3]);
        *(uint4*)(hp +  8) = make_uint4(s0[4], s0[5], s0[6], s0[7]);
        *(uint4*)(hp + 16) = make_uint4(s1[0], s1[1], s1[2], s1[3]);
        *(uint4*)(hp + 24) = make_uint4(s1[4], s1[5], s1[6], s1[7]);
        __syncthreads();
    }

    float* pp = &g_part[((size_t)blockIdx.x * 64 + b) * 256 + (size_t)(2 * kp) * 16];
#pragma unroll
    for (int op = 0; op < 8; op++) {
        float2 v0 = unpack2(acc0[op]);
        float2 v1 = unpack2(acc1[op]);
        pp[2 * op]          = v0.x;
        pp[2 * op + 1]      = v0.y;
        pp[16 + 2 * op]     = v1.x;
        pp[16 + 2 * op + 1] = v1.y;
    }
}

// Routing pass over stored fp16 hats. grid 1024 = (b<64)*(g<16), block 256.
// Warp handles one n at a time: lane l -> k = l>>1, o-half = (l&1)*8.
__global__ void __launch_bounds__(256) route_kernel() {
    const int b = blockIdx.x >> 4, g = blockIdx.x & 15;
    const int w = threadIdx.x >> 5, l = threadIdx.x & 31;
    const int k = l >> 1, oh = (l & 1) * 8;

    ull r[4];
    {
        const float* rp = g_route + ((size_t)b * 16 + k) * 16 + oh;
        ulonglong2 a = *(const ulonglong2*)(rp);
        ulonglong2 c = *(const ulonglong2*)(rp + 4);
        r[0] = a.x; r[1] = a.y; r[2] = c.x; r[3] = c.y;
    }

    ull acc[4] = {0ull, 0ull, 0ull, 0ull};
    const size_t lane_off = (size_t)k * 16 + oh;

#pragma unroll 4
    for (int i = 0; i < 16; i++) {
        int n = g * 128 + i * 8 + w;
        uint4 hv = *(const uint4*)(g_hats + ((size_t)b * 2048 + n) * 256 + lane_off);
        ull h[4];
        h[0] = h2f2(hv.x); h[1] = h2f2(hv.y); h[2] = h2f2(hv.z); h[3] = h2f2(hv.w);

        ull t = mul2(h[0], r[0]);
        t = fma2(h[1], r[1], t);
        t = fma2(h[2], r[2], t);
        t = fma2(h[3], r[3], t);
        float2 q = unpack2(t);
        float bh = q.x + q.y;
        float bk = bh + __shfl_xor_sync(0xffffffffu, bh, 1);   // bias for this k

        float m = bk;
        m = fmaxf(m, __shfl_xor_sync(0xffffffffu, m, 2));
        m = fmaxf(m, __shfl_xor_sync(0xffffffffu, m, 4));
        m = fmaxf(m, __shfl_xor_sync(0xffffffffu, m, 8));
        m = fmaxf(m, __shfl_xor_sync(0xffffffffu, m, 16));
        float e = __expf(bk - m);
        float s = e;
        s += __shfl_xor_sync(0xffffffffu, s, 2);
        s += __shfl_xor_sync(0xffffffffu, s, 4);
        s += __shfl_xor_sync(0xffffffffu, s, 8);
        s += __shfl_xor_sync(0xffffffffu, s, 16);
        float c = __fdividef(e, s);
        ull c2 = pack2(c);
        acc[0] = fma2(c2, h[0], acc[0]);
        acc[1] = fma2(c2, h[1], acc[1]);
        acc[2] = fma2(c2, h[2], acc[2]);
        acc[3] = fma2(c2, h[3], acc[3]);
    }

    __shared__ ull red[8][32][4];   // 8 KB
#pragma unroll
    for (int j = 0; j < 4; j++) red[w][l][j] = acc[j];
    __syncthreads();
    if (threadIdx.x < 128) {
        const int u = threadIdx.x & 3, ll = threadIdx.x >> 2;
        ull s = red[0][ll][u];
#pragma unroll
        for (int ww = 1; ww < 8; ww++) s = add2(s, red[ww][ll][u]);
        float2 v = unpack2(s);
        const int off = (ll >> 1) * 16 + (ll & 1) * 8 + u * 2;
        float* dst = g_part2 + ((size_t)g * 64 + b) * 256 + off;
        dst[0] = v.x; dst[1] = v.y;
    }
}

// Reduce cnt chunks (from g_part if src==0 else g_part2), squash, update
// route / emit output. grid 64 (b), block 256 (k*16+o).
__global__ void squash_kernel(int src, int cnt, float scale, int mode,
                              float* __restrict__ out) {
    const int tid = threadIdx.x;
    const int bidx = blockIdx.x;
    const float* p = (src == 0 ? g_part : g_part2) + (size_t)bidx * 256 + tid;
    float s = 0.f;
#pragma unroll 8
    for (int j = 0; j < cnt; j++) s += p[(size_t)j * 16384];
    s *= scale;
    float s2 = s * s;
    s2 += __shfl_xor_sync(0xffffffffu, s2, 1);
    s2 += __shfl_xor_sync(0xffffffffu, s2, 2);
    s2 += __shfl_xor_sync(0xffffffffu, s2, 4);
    s2 += __shfl_xor_sync(0xffffffffu, s2, 8);
    float sc = s2 / ((1.0f + s2) * sqrtf(s2));
    float v = sc * s;
    int idx = bidx * 256 + tid;
    if (mode == 0)      g_route[idx] = v;
    else if (mode == 1) g_route[idx] += v;
    else                out[idx] = v;
}

extern "C" void kernel_launch(void* const* d_in, const int* in_sizes, int n_in,
                              void* d_out, int out_size) {
    const float* x = (const float*)d_in[0];   // [64, 2048, 8]
    const float* W = (const float*)d_in[1];   // [2048, 16, 8, 16]
    float* out = (float*)d_out;               // [64, 16, 16]
    (void)in_sizes; (void)n_in; (void)out_size;

    pass1_kernel<<<NBLK, THREADS>>>(x, W);                  // hats (fp16) + s0 partials
    squash_kernel<<<64, 256>>>(0, NBLK, 1.0f / 16.0f, 0, out); // out0 -> route
    route_kernel<<<1024, 256>>>();                          // s1 partials (16)
    squash_kernel<<<64, 256>>>(1, 16, 1.0f, 1, out);        // route += out1
    route_kernel<<<1024, 256>>>();                          // s2 partials (16)
    squash_kernel<<<64, 256>>>(1, 16, 1.0f, 2, out);        // final output
}

// round 4
// speedup vs baseline: 1.1369x; 1.1369x over previous
#include <cuda_runtime.h>

// CapsuleBlock: B=64, N=2048, D_in=8, K=16, O=16, 3 routing iters.
// R4: pass1 restructured for 4-way b register reuse of W smem reads
// (FMA-bound, not LDS-bound). route restructured: half-warp per (b,n),
// lane = k, o in-thread -> 4 shuffles per n instead of 9.

#define NBLK   148
#define CHUNK  14          // 148*14 = 2072 >= 2048

__device__ float g_part [(size_t)NBLK * 16384];          // pass1 partials [blk][b][256]
__device__ float g_part2[(size_t)16 * 16384];            // route partials [g][b][256]
__device__ float g_route[16384];                         // routing vector [b][k][o]
__device__ __align__(16) unsigned short g_hats[(size_t)64 * 2048 * 256]; // fp16 hats

typedef unsigned long long ull;

__device__ __forceinline__ ull pack2(float v) {
    ull r; asm("mov.b64 %0, {%1, %1};" : "=l"(r) : "f"(v)); return r;
}
__device__ __forceinline__ ull fma2(ull a, ull b, ull c) {
    ull d; asm("fma.rn.f32x2 %0, %1, %2, %3;" : "=l"(d) : "l"(a), "l"(b), "l"(c)); return d;
}
__device__ __forceinline__ ull mul2(ull a, ull b) {
    ull d; asm("mul.rn.f32x2 %0, %1, %2;" : "=l"(d) : "l"(a), "l"(b)); return d;
}
__device__ __forceinline__ ull add2(ull a, ull b) {
    ull d; asm("add.rn.f32x2 %0, %1, %2;" : "=l"(d) : "l"(a), "l"(b)); return d;
}
__device__ __forceinline__ float2 unpack2(ull v) {
    float2 r; asm("mov.b64 {%0, %1}, %2;" : "=f"(r.x), "=f"(r.y) : "l"(v)); return r;
}
__device__ __forceinline__ unsigned cvtf16x2(float lo, float hi) {
    unsigned r; asm("cvt.rn.f16x2.f32 %0, %1, %2;" : "=r"(r) : "f"(hi), "f"(lo)); return r;
}
__device__ __forceinline__ ull h2f2(unsigned w) {
    ull d;
    asm("{ .reg .b16 l, h; .reg .f32 fl, fh;\n\t"
        "mov.b32 {l, h}, %1;\n\t"
        "cvt.f32.f16 fl, l;\n\t"
        "cvt.f32.f16 fh, h;\n\t"
        "mov.b64 %0, {fl, fh}; }"
        : "=l"(d) : "r"(w));
    return d;
}

// pass1: hats[b,n,k,o] = sum_d x[b,n,d] W[n,k,d,o]; s0 += hats; store fp16.
// thread = (k, bq): k = tid>>4 (16), bq = tid&15 (16); b = 4*bq + j, j=0..3.
__global__ void __launch_bounds__(256, 1)
pass1_kernel(const float* __restrict__ x, const float* __restrict__ W) {
    __shared__ __align__(16) float Ws[8][4][17][4];   // [d][oq][k(+pad)][4o], ~8.7KB
    __shared__ __align__(16) float xs[CHUNK][8][68];  // [ln][d][b(+pad)], ~30.5KB

    const int tid = threadIdx.x;
    const int k  = tid >> 4;
    const int bq = tid & 15;
    const int n0 = blockIdx.x * CHUNK;
    int nmax = 2048 - n0; if (nmax > CHUNK) nmax = CHUNK; if (nmax < 0) nmax = 0;

    // ---- stage x: [ln][d][b]; conflict-free scatter (pad 68) ----
    for (int i = tid; i < nmax * 128; i += 256) {
        int ln = i >> 7, r = i & 127, b = r >> 1, dq = r & 1;
        float4 v = *(const float4*)(x + ((size_t)b * 2048 + (size_t)(n0 + ln)) * 8 + dq * 4);
        xs[ln][dq * 4 + 0][b] = v.x;
        xs[ln][dq * 4 + 1][b] = v.y;
        xs[ln][dq * 4 + 2][b] = v.z;
        xs[ln][dq * 4 + 3][b] = v.w;
    }

    // ---- W staging map: thread t covers global floats [t*8, t*8+8) of W[n] ----
    const int kw  = tid >> 4;            // k of staged chunk
    const int dw  = (tid >> 1) & 7;      // d
    const int oq0 = 2 * (tid & 1);       // o-quad pair
    const size_t woff = (size_t)tid * 8;
    float4 wreg0 = make_float4(0.f,0.f,0.f,0.f), wreg1 = wreg0;
    if (nmax > 0) {
        wreg0 = *(const float4*)(W + (size_t)n0 * 2048 + woff);
        wreg1 = *(const float4*)(W + (size_t)n0 * 2048 + woff + 4);
    }

    ull acc[4][8];
#pragma unroll
    for (int j = 0; j < 4; j++)
#pragma unroll
        for (int op = 0; op < 8; op++) acc[j][op] = 0ull;

    for (int ln = 0; ln < nmax; ln++) {
        *(float4*)&Ws[dw][oq0    ][kw][0] = wreg0;
        *(float4*)&Ws[dw][oq0 + 1][kw][0] = wreg1;
        __syncthreads();
        if (ln + 1 < nmax) {
            wreg0 = *(const float4*)(W + (size_t)(n0 + ln + 1) * 2048 + woff);
            wreg1 = *(const float4*)(W + (size_t)(n0 + ln + 1) * 2048 + woff + 4);
        }

        ull h[4][8];
#pragma unroll
        for (int d = 0; d < 8; d++) {
            float4 xq = *(const float4*)&xs[ln][d][4 * bq];
            ull xd[4];
            xd[0] = pack2(xq.x); xd[1] = pack2(xq.y);
            xd[2] = pack2(xq.z); xd[3] = pack2(xq.w);
#pragma unroll
            for (int oq = 0; oq < 4; oq++) {
                ulonglong2 wv = *(const ulonglong2*)&Ws[d][oq][k][0];
#pragma unroll
                for (int j = 0; j < 4; j++) {
                    if (d == 0) {
                        h[j][2 * oq]     = mul2(xd[j], wv.x);
                        h[j][2 * oq + 1] = mul2(xd[j], wv.y);
                    } else {
                        h[j][2 * oq]     = fma2(xd[j], wv.x, h[j][2 * oq]);
                        h[j][2 * oq + 1] = fma2(xd[j], wv.y, h[j][2 * oq + 1]);
                    }
                }
            }
        }
        // accumulate s0 + convert/store hats fp16 (32B per b, sector-aligned)
#pragma unroll
        for (int j = 0; j < 4; j++) {
            unsigned st[8];
#pragma unroll
            for (int op = 0; op < 8; op++) {
                acc[j][op] = add2(acc[j][op], h[j][op]);
                float2 a = unpack2(h[j][op]);
                st[op] = cvtf16x2(a.x, a.y);
            }
            unsigned short* hp = g_hats + ((size_t)(4 * bq + j) * 2048 + (size_t)(n0 + ln)) * 256 + (size_t)k * 16;
            *(uint4*)(hp)     = make_uint4(st[0], st[1], st[2], st[3]);
            *(uint4*)(hp + 8) = make_uint4(st[4], st[5], st[6], st[7]);
        }
        __syncthreads();
    }

#pragma unroll
    for (int j = 0; j < 4; j++) {
        float* pp = &g_part[((size_t)blockIdx.x * 64 + (size_t)(4 * bq + j)) * 256 + (size_t)k * 16];
#pragma unroll
        for (int op = 0; op < 8; op++) {
            float2 v = unpack2(acc[j][op]);
            pp[2 * op]     = v.x;
            pp[2 * op + 1] = v.y;
        }
    }
}

// route pass: half-warp per (b,n); lane = k holds all 16 o.
// grid 1024 = (b<64)*(g<16), block 256 (8 warps). Warp-iter: 2 n (1KB contig).
__global__ void __launch_bounds__(256) route_kernel() {
    const int b = blockIdx.x >> 4, g = blockIdx.x & 15;
    const int w = threadIdx.x >> 5, l = threadIdx.x & 31;
    const int hf = l >> 4, kk = l & 15;

    ull rr[8];
    {
        const ull* rp = (const ull*)(g_route + ((size_t)b * 16 + kk) * 16);
#pragma unroll
        for (int i = 0; i < 8; i++) rr[i] = rp[i];
    }

    ull acc[8];
#pragma unroll
    for (int i = 0; i < 8; i++) acc[i] = 0ull;

#pragma unroll
    for (int it = 0; it < 8; it++) {
        int n = g * 128 + it * 16 + w * 2 + hf;
        const uint4* hp = (const uint4*)(g_hats + ((size_t)b * 2048 + n) * 256 + (size_t)kk * 16);
        uint4 v0 = hp[0], v1 = hp[1];
        ull hh[8];
        hh[0] = h2f2(v0.x); hh[1] = h2f2(v0.y); hh[2] = h2f2(v0.z); hh[3] = h2f2(v0.w);
        hh[4] = h2f2(v1.x); hh[5] = h2f2(v1.y); hh[6] = h2f2(v1.z); hh[7] = h2f2(v1.w);

        ull t = mul2(hh[0], rr[0]);
#pragma unroll
        for (int i = 1; i < 8; i++) t = fma2(hh[i], rr[i], t);
        float2 q = unpack2(t);
        float bias = q.x + q.y;                       // thread-local: no shuffle

        // softmax over 16 k = 16 lanes of this half-warp (xor bits 0..3)
        float m = bias;
        m = fmaxf(m, __shfl_xor_sync(0xffffffffu, m, 1));
        m = fmaxf(m, __shfl_xor_sync(0xffffffffu, m, 2));
        m = fmaxf(m, __shfl_xor_sync(0xffffffffu, m, 4));
        m = fmaxf(m, __shfl_xor_sync(0xffffffffu, m, 8));
        float e = __expf(bias - m);
        float s = e;
        s += __shfl_xor_sync(0xffffffffu, s, 1);
        s += __shfl_xor_sync(0xffffffffu, s, 2);
        s += __shfl_xor_sync(0xffffffffu, s, 4);
        s += __shfl_xor_sync(0xffffffffu, s, 8);
        float c = __fdividef(e, s);
        ull c2 = pack2(c);
#pragma unroll
        for (int i = 0; i < 8; i++) acc[i] = fma2(c2, hh[i], acc[i]);
    }

    // combine the two half-warps (same kk), then cross-warp via smem
    __shared__ float red[8][256];
    float ax[8], ay[8];
#pragma unroll
    for (int i = 0; i < 8; i++) {
        float2 a = unpack2(acc[i]);
        a.x += __shfl_xor_sync(0xffffffffu, a.x, 16);
        a.y += __shfl_xor_sync(0xffffffffu, a.y, 16);
        ax[i] = a.x; ay[i] = a.y;
    }
    if (hf == 0) {
        float* dst = &red[w][kk * 16];
#pragma unroll
        for (int i = 0; i < 8; i++) { dst[2 * i] = ax[i]; dst[2 * i + 1] = ay[i]; }
    }
    __syncthreads();
    {
        const int t = threadIdx.x;
        float s = 0.f;
#pragma unroll
        for (int ww = 0; ww < 8; ww++) s += red[ww][t];
        g_part2[((size_t)g * 64 + b) * 256 + t] = s;
    }
}

// Reduce cnt chunks (g_part if src==0 else g_part2), squash, route/output.
__global__ void squash_kernel(int src, int cnt, float scale, int mode,
                              float* __restrict__ out) {
    const int tid = threadIdx.x;
    const int bidx = blockIdx.x;
    const float* p = (src == 0 ? g_part : g_part2) + (size_t)bidx * 256 + tid;
    float s = 0.f;
#pragma unroll 8
    for (int j = 0; j < cnt; j++) s += p[(size_t)j * 16384];
    s *= scale;
    float s2 = s * s;
    s2 += __shfl_xor_sync(0xffffffffu, s2, 1);
    s2 += __shfl_xor_sync(0xffffffffu, s2, 2);
    s2 += __shfl_xor_sync(0xffffffffu, s2, 4);
    s2 += __shfl_xor_sync(0xffffffffu, s2, 8);
    float sc = s2 / ((1.0f + s2) * sqrtf(s2));
    float v = sc * s;
    int idx = bidx * 256 + tid;
    if (mode == 0)      g_route[idx] = v;
    else if (mode == 1) g_route[idx] += v;
    else                out[idx] = v;
}

extern "C" void kernel_launch(void* const* d_in, const int* in_sizes, int n_in,
                              void* d_out, int out_size) {
    const float* x = (const float*)d_in[0];   // [64, 2048, 8]
    const float* W = (const float*)d_in[1];   // [2048, 16, 8, 16]
    float* out = (float*)d_out;               // [64, 16, 16]
    (void)in_sizes; (void)n_in; (void)out_size;

    pass1_kernel<<<NBLK, 256>>>(x, W);                     // hats (fp16) + s0 partials
    squash_kernel<<<64, 256>>>(0, NBLK, 1.0f / 16.0f, 0, out); // out0 -> route
    route_kernel<<<1024, 256>>>();                         // s1 partials (16)
    squash_kernel<<<64, 256>>>(1, 16, 1.0f, 1, out);       // route += out1
    route_kernel<<<1024, 256>>>();                         // s2 partials (16)
    squash_kernel<<<64, 256>>>(1, 16, 1.0f, 2, out);       // final output
}